// round 3
// baseline (speedup 1.0000x reference)
#include <cuda_runtime.h>

// Problem constants
#define Hh   256
#define Ll   512
#define Nn   512
#define HV4  (Hh / 4)          // 64 float4 per row
#define TOTAL_V4 (Nn * Ll * HV4)

// Positional-embedding table, recomputed every launch (deterministic).
// 512 * 256 floats = 512 KB -> L2-resident during the main kernel.
__device__ float g_pos[Ll * Hh];

__global__ void pos_kernel() {
    int idx = blockIdx.x * blockDim.x + threadIdx.x;   // over Ll * (Hh/2) pairs
    if (idx >= Ll * (Hh / 2)) return;
    int s = idx >> 7;            // / (Hh/2)
    int i = idx & 127;           // % (Hh/2)
    // omega_inv = 10000^(2i/H); ang = s / omega_inv
    // Compute in fp32 matching the reference's fp32 math closely:
    // ang = s * 10000^(-2i/H) = s * exp(-(2i/H) * ln(10000))
    const float LN1E4 = 9.210340371976184f;   // ln(10000)
    float e = -(2.0f * (float)i / (float)Hh) * LN1E4;
    float ang = (float)s * expf(e);
    g_pos[(s << 8) + 2 * i]     = sinf(ang);
    g_pos[(s << 8) + 2 * i + 1] = cosf(ang);
}

__global__ __launch_bounds__(256) void embed_kernel(
    const float* __restrict__ u,          // (N, L, 3)
    const float* __restrict__ w_num,      // (T*H, 1) -> w_t[t][h] = w_num[t*H + h]
    const float* __restrict__ cat_table,  // (n_emb, H)
    const int*   __restrict__ num_pt,     // (L/2,)
    const int*   __restrict__ easy,       // (MAXC*T,)
    float4*      __restrict__ out)        // (N, L, H) as float4
{
    int idx = blockIdx.x * blockDim.x + threadIdx.x;   // [0, N*L*64)
    if (idx >= TOTAL_V4) return;
    int h4 = idx & (HV4 - 1);
    int s  = (idx >> 6) & (Ll - 1);
    int n  = idx >> 15;

    const float4* __restrict__ pos4 = (const float4*)g_pos;
    float4 p = pos4[(s << 6) + h4];

    const float* __restrict__ urow = u + (size_t)((n << 9) + s) * 3;

    float4 r;
    if (s & 1) {
        // categorical row: big = round(u2*64 + u0); e = easy[big]
        float u0 = __ldg(urow + 0);
        float u2 = __ldg(urow + 2);
        int big = __float2int_rn(u2 * 64.0f + u0);
        int e   = __ldg(easy + big);
        const float4* __restrict__ t4 = (const float4*)cat_table;
        float4 c = t4[(e << 6) + h4];
        r.x = c.x + p.x;
        r.y = c.y + p.y;
        r.z = c.z + p.z;
        r.w = c.w + p.w;
    } else {
        // numeric row: v = 2*(u1-0.5); out = v * w_t[pt] + pos
        float u1 = __ldg(urow + 1);
        float v  = 2.0f * (u1 - 0.5f);
        int pt   = __ldg(num_pt + (s >> 1));
        const float4* __restrict__ w4 = (const float4*)w_num;
        float4 w = w4[(pt << 6) + h4];
        r.x = fmaf(v, w.x, p.x);
        r.y = fmaf(v, w.y, p.y);
        r.z = fmaf(v, w.z, p.z);
        r.w = fmaf(v, w.w, p.w);
    }
    out[idx] = r;
}

extern "C" void kernel_launch(void* const* d_in, const int* in_sizes, int n_in,
                              void* d_out, int out_size) {
    // metadata order: u_in, w_num, cat_table, cat_rows, num_rows,
    //                 num_param_types, easy_index
    const float* u         = (const float*)d_in[0];
    const float* w_num     = (const float*)d_in[1];
    const float* cat_table = (const float*)d_in[2];
    const int*   num_pt    = (const int*)  d_in[5];
    const int*   easy      = (const int*)  d_in[6];
    float4* out = (float4*)d_out;

    // 1) rebuild positional table (deterministic, graph-capturable)
    int pos_elems = Ll * (Hh / 2);
    pos_kernel<<<(pos_elems + 255) / 256, 256>>>();

    // 2) fused embedding fill
    embed_kernel<<<(TOTAL_V4 + 255) / 256, 256>>>(u, w_num, cat_table, num_pt, easy, out);
}

// round 4
// speedup vs baseline: 1.7230x; 1.7230x over previous
#include <cuda_runtime.h>

// Problem constants
#define Hh   256
#define Ll   512
#define Nn   512
#define HV4  (Hh / 4)          // 64 float4 per row
#define NCHUNK 8
#define NSPLIT (Nn / NCHUNK)   // 64
#define TOTAL_THREADS (Ll * HV4 * NSPLIT)   // 2,097,152

// Positional-embedding table, recomputed every launch (deterministic).
__device__ float g_pos[Ll * Hh];

__global__ void pos_kernel() {
    int idx = blockIdx.x * blockDim.x + threadIdx.x;   // Ll * (Hh/2) pairs
    if (idx >= Ll * (Hh / 2)) return;
    int s = idx >> 7;            // / (Hh/2)
    int i = idx & 127;           // % (Hh/2)
    // ang = s * 10000^(-2i/H) = s * exp(-(2i/H) * ln(10000))
    const float LN1E4 = 9.210340371976184f;   // ln(10000)
    float e = -(2.0f * (float)i / (float)Hh) * LN1E4;
    float ang = (float)s * expf(e);
    g_pos[(s << 8) + 2 * i]     = sinf(ang);
    g_pos[(s << 8) + 2 * i + 1] = cosf(ang);
}

__global__ __launch_bounds__(256) void embed_kernel(
    const float* __restrict__ u,          // (N, L, 3)
    const float* __restrict__ w_num,      // (T*H,) -> w_t[t][h] = w_num[t*H + h]
    const float* __restrict__ cat_table,  // (n_emb, H)
    const int*   __restrict__ num_pt,     // (L/2,)
    const int*   __restrict__ easy,       // (MAXC*T,)
    float4*      __restrict__ out)        // (N, L, H) as float4
{
    int t  = blockIdx.x * blockDim.x + threadIdx.x;
    int h4 = t & (HV4 - 1);           // 0..63
    int s  = (t >> 6) & (Ll - 1);     // 0..511
    int nc = t >> 15;                 // 0..63
    int n0 = nc << 3;                 // first n of this chunk

    const float4* __restrict__ pos4 = (const float4*)g_pos;
    float4 p = pos4[(s << 6) + h4];

    if (s & 1) {
        // categorical rows: gather per n
        const float4* __restrict__ t4 = (const float4*)cat_table;
        #pragma unroll
        for (int j = 0; j < NCHUNK; j++) {
            int n = n0 + j;
            const float* urow = u + (size_t)((n << 9) + s) * 3;
            float u0 = __ldg(urow + 0);
            float u2 = __ldg(urow + 2);
            int big = __float2int_rn(u2 * 64.0f + u0);
            int e   = __ldg(easy + big);
            float4 c = t4[(e << 6) + h4];
            float4 r;
            r.x = c.x + p.x;
            r.y = c.y + p.y;
            r.z = c.z + p.z;
            r.w = c.w + p.w;
            __stcs(out + ((size_t)((n << 9) + s) << 6) + h4, r);
        }
    } else {
        // numeric rows: weight row is invariant over n
        int pt = __ldg(num_pt + (s >> 1));
        const float4* __restrict__ w4 = (const float4*)w_num;
        float4 w = w4[(pt << 6) + h4];
        #pragma unroll
        for (int j = 0; j < NCHUNK; j++) {
            int n = n0 + j;
            float u1 = __ldg(u + (size_t)((n << 9) + s) * 3 + 1);
            float v  = 2.0f * (u1 - 0.5f);
            float4 r;
            r.x = fmaf(v, w.x, p.x);
            r.y = fmaf(v, w.y, p.y);
            r.z = fmaf(v, w.z, p.z);
            r.w = fmaf(v, w.w, p.w);
            __stcs(out + ((size_t)((n << 9) + s) << 6) + h4, r);
        }
    }
}

extern "C" void kernel_launch(void* const* d_in, const int* in_sizes, int n_in,
                              void* d_out, int out_size) {
    // metadata order: u_in, w_num, cat_table, cat_rows, num_rows,
    //                 num_param_types, easy_index
    const float* u         = (const float*)d_in[0];
    const float* w_num     = (const float*)d_in[1];
    const float* cat_table = (const float*)d_in[2];
    const int*   num_pt    = (const int*)  d_in[5];
    const int*   easy      = (const int*)  d_in[6];
    float4* out = (float4*)d_out;

    // 1) rebuild positional table (deterministic, graph-capturable)
    int pos_elems = Ll * (Hh / 2);
    pos_kernel<<<(pos_elems + 255) / 256, 256>>>();

    // 2) fused embedding fill, n-chunked so per-(s,h4) invariants are hoisted
    embed_kernel<<<TOTAL_THREADS / 256, 256>>>(u, w_num, cat_table, num_pt, easy, out);
}